// round 1
// baseline (speedup 1.0000x reference)
#include <cuda_runtime.h>
#include <math.h>
#include <stdint.h>

#define D_MODEL 1024
#define N_HEADS 16
#define D_HEAD  64
#define D_FF    4096
#define BATCH   2
#define SEQ     2048
#define NTOK    (BATCH*SEQ)

// ---------------- scratch (no cudaMalloc allowed) ----------------
__device__ float g_h  [NTOK*D_MODEL];
__device__ float g_q  [NTOK*D_MODEL];
__device__ float g_k  [NTOK*D_MODEL];
__device__ float g_v  [NTOK*D_MODEL];
__device__ float g_c  [NTOK*N_HEADS];
__device__ float g_ctx[NTOK*D_MODEL];
__device__ float g_x1 [NTOK*D_MODEL];
__device__ float g_h2 [NTOK*D_MODEL];
__device__ float g_ff [NTOK*D_FF];

// ---------------- LayerNorm: one block per token row ----------------
__global__ __launch_bounds__(256) void ln_kernel(
    const float* __restrict__ x, const float* __restrict__ g,
    const float* __restrict__ b, float* __restrict__ out)
{
    int row = blockIdx.x;
    int tid = threadIdx.x;
    const float4* xr = (const float4*)(x + (size_t)row * D_MODEL);
    float4 v = xr[tid];                       // 256*4 = 1024
    float s  = v.x + v.y + v.z + v.w;
    float s2 = v.x*v.x + v.y*v.y + v.z*v.z + v.w*v.w;

    __shared__ float red[18];
    #pragma unroll
    for (int off = 16; off > 0; off >>= 1) {
        s  += __shfl_xor_sync(0xffffffffu, s,  off);
        s2 += __shfl_xor_sync(0xffffffffu, s2, off);
    }
    int w = tid >> 5, lane = tid & 31;
    if (lane == 0) { red[w] = s; red[8 + w] = s2; }
    __syncthreads();
    if (tid == 0) {
        float a = 0.f, c2 = 0.f;
        #pragma unroll
        for (int i = 0; i < 8; i++) { a += red[i]; c2 += red[8 + i]; }
        red[16] = a; red[17] = c2;
    }
    __syncthreads();
    float mu  = red[16] * (1.0f / D_MODEL);
    float var = red[17] * (1.0f / D_MODEL) - mu * mu;
    float inv = rsqrtf(var + 1e-5f);

    float4 gg = ((const float4*)g)[tid];
    float4 bb = ((const float4*)b)[tid];
    float4 o;
    o.x = (v.x - mu) * inv * gg.x + bb.x;
    o.y = (v.y - mu) * inv * gg.y + bb.y;
    o.z = (v.z - mu) * inv * gg.z + bb.z;
    o.w = (v.w - mu) * inv * gg.w + bb.w;
    ((float4*)(out + (size_t)row * D_MODEL))[tid] = o;
}

// ---------------- generic tiled SGEMM: C = act(A@W + bias) (+resid) ----------------
// A[M,K] row-major, W[K,N] row-major. 64x64 tile, kt=16, 256 thr, 4x4/thread.
__device__ __forceinline__ float gelu_exact(float x) {
    return 0.5f * x * (1.0f + erff(x * 0.70710678118654752f));
}

__global__ __launch_bounds__(256) void gemm64(
    const float* __restrict__ A, const float* __restrict__ W,
    const float* __restrict__ bias, const float* __restrict__ resid,
    float* __restrict__ C, int M, int N, int K, int act)
{
    __shared__ float As[16][64];   // As[k][m]
    __shared__ float Ws[16][64];   // Ws[k][n]

    int tid = threadIdx.x;
    int tx = tid & 15, ty = tid >> 4;
    int nb = blockIdx.x * 64;
    int mb = blockIdx.y * 64;

    float acc[4][4] = {};

    int am  = tid >> 2;            // 0..63
    int ak4 = (tid & 3) * 4;       // 0,4,8,12
    int wn4 = (tid & 15) * 4;
    int wk  = tid >> 4;            // 0..15
    const float* Aptr = A + (size_t)(mb + am) * K + ak4;
    const float* Wptr = W + (size_t)wk * N + nb + wn4;

    for (int k0 = 0; k0 < K; k0 += 16) {
        float4 av = *(const float4*)(Aptr + k0);
        As[ak4 + 0][am] = av.x;
        As[ak4 + 1][am] = av.y;
        As[ak4 + 2][am] = av.z;
        As[ak4 + 3][am] = av.w;
        *(float4*)(&Ws[wk][wn4]) = *(const float4*)(Wptr + (size_t)k0 * N);
        __syncthreads();
        #pragma unroll
        for (int kk = 0; kk < 16; kk++) {
            float4 a4 = *(const float4*)(&As[kk][ty * 4]);
            float4 w4 = *(const float4*)(&Ws[kk][tx * 4]);
            float aa[4] = {a4.x, a4.y, a4.z, a4.w};
            float ww[4] = {w4.x, w4.y, w4.z, w4.w};
            #pragma unroll
            for (int i = 0; i < 4; i++)
                #pragma unroll
                for (int j = 0; j < 4; j++)
                    acc[i][j] = fmaf(aa[i], ww[j], acc[i][j]);
        }
        __syncthreads();
    }

    float4 bv = *(const float4*)(bias + nb + tx * 4);
    float bb[4] = {bv.x, bv.y, bv.z, bv.w};
    #pragma unroll
    for (int i = 0; i < 4; i++) {
        int r = mb + ty * 4 + i;
        float o[4];
        #pragma unroll
        for (int j = 0; j < 4; j++) {
            float vv = acc[i][j] + bb[j];
            if (act == 1) vv = gelu_exact(vv);
            o[j] = vv;
        }
        size_t base = (size_t)r * N + nb + tx * 4;
        if (resid) {
            float4 rv = *(const float4*)(resid + base);
            o[0] += rv.x; o[1] += rv.y; o[2] += rv.z; o[3] += rv.w;
        }
        *(float4*)(C + base) = make_float4(o[0], o[1], o[2], o[3]);
    }
}

// ---------------- forget gate: logf = log_sigmoid(h @ wf + bf) ----------------
__global__ __launch_bounds__(256) void fgate_kernel(
    const float* __restrict__ h, const float* __restrict__ wf,
    const float* __restrict__ bf, float* __restrict__ logf)
{
    int t   = blockIdx.x;
    int tid = threadIdx.x;
    int hd  = tid >> 4;     // 0..15 head
    int ln  = tid & 15;
    const float* hr = h + (size_t)t * D_MODEL;
    float s = 0.f;
    #pragma unroll 8
    for (int k = ln; k < D_MODEL; k += 16)
        s = fmaf(hr[k], wf[(size_t)k * N_HEADS + hd], s);
    #pragma unroll
    for (int off = 8; off > 0; off >>= 1)
        s += __shfl_xor_sync(0xffffffffu, s, off);
    if (ln == 0) {
        float z = s + bf[hd];
        float ls = (z >= 0.f) ? -log1pf(expf(-z)) : (z - log1pf(expf(z)));
        logf[(size_t)t * N_HEADS + hd] = ls;
    }
}

// ---------------- in-place cumsum over sequence per (b,h) ----------------
__global__ __launch_bounds__(256) void cumsum_kernel(float* __restrict__ c)
{
    int bh = blockIdx.x;
    int b  = bh >> 4, h = bh & 15;
    int tid = threadIdx.x;
    const int CHUNK = SEQ / 256;   // 8
    float vals[CHUNK];
    float run = 0.f;
    size_t base = (size_t)b * SEQ * N_HEADS + h;
    #pragma unroll
    for (int u = 0; u < CHUNK; u++) {
        run += c[base + (size_t)(tid * CHUNK + u) * N_HEADS];
        vals[u] = run;
    }
    __shared__ float tot[256];
    tot[tid] = run;
    __syncthreads();
    for (int off = 1; off < 256; off <<= 1) {
        float t = (tid >= off) ? tot[tid - off] : 0.f;
        __syncthreads();
        tot[tid] += t;
        __syncthreads();
    }
    float offs = tot[tid] - run;   // exclusive prefix
    #pragma unroll
    for (int u = 0; u < CHUNK; u++)
        c[base + (size_t)(tid * CHUNK + u) * N_HEADS] = vals[u] + offs;
}

// ---------------- flash attention with forgetting decay ----------------
// logits = (q.k)/8 + c_i - c_j ; c_i is row-constant -> dropped (softmax invariant).
__global__ __launch_bounds__(256) void attn_kernel(
    const float* __restrict__ Q, const float* __restrict__ Kp,
    const float* __restrict__ Vp, const float* __restrict__ Cdec,
    float* __restrict__ Out)
{
    extern __shared__ float sm[];
    float* Qs = sm;               // [64][64]
    float* Ks = Qs + 64 * 64;     // [64][65]
    float* Vs = Ks + 64 * 65;     // [64][64]
    float* Ps = Vs + 64 * 64;     // [64][65]

    int qt = blockIdx.x, h = blockIdx.y, b = blockIdx.z;
    int tid = threadIdx.x;
    int tx = tid & 15, ty = tid >> 4;
    int qbase = qt * 64;
    size_t rowbase = (size_t)b * SEQ;

    const float* qg = Q + (rowbase + qbase) * D_MODEL + h * D_HEAD;
    #pragma unroll
    for (int i = 0; i < 4; i++) {
        int e = tid + i * 256;
        int r = e >> 4, d4 = e & 15;
        *(float4*)(Qs + r * 64 + d4 * 4) =
            *(const float4*)(qg + (size_t)r * D_MODEL + d4 * 4);
    }

    float m[4], l[4], acc[4][4];
    #pragma unroll
    for (int i = 0; i < 4; i++) {
        m[i] = -1e30f; l[i] = 0.f;
        #pragma unroll
        for (int j = 0; j < 4; j++) acc[i][j] = 0.f;
    }
    __syncthreads();

    for (int kt = 0; kt <= qt; kt++) {
        int kbase = kt * 64;
        const float* kg = Kp + (rowbase + kbase) * D_MODEL + h * D_HEAD;
        const float* vg = Vp + (rowbase + kbase) * D_MODEL + h * D_HEAD;
        #pragma unroll
        for (int i = 0; i < 4; i++) {
            int e = tid + i * 256;
            int r = e >> 4, d4 = e & 15;
            float4 kv = *(const float4*)(kg + (size_t)r * D_MODEL + d4 * 4);
            float* kd = Ks + r * 65 + d4 * 4;
            kd[0] = kv.x; kd[1] = kv.y; kd[2] = kv.z; kd[3] = kv.w;
            *(float4*)(Vs + r * 64 + d4 * 4) =
                *(const float4*)(vg + (size_t)r * D_MODEL + d4 * 4);
        }
        float cj[4];
        #pragma unroll
        for (int j = 0; j < 4; j++)
            cj[j] = Cdec[(rowbase + kbase + tx * 4 + j) * N_HEADS + h];
        __syncthreads();

        // S = Q K^T
        float s[4][4] = {};
        #pragma unroll 8
        for (int d = 0; d < 64; d++) {
            float qv[4], kv[4];
            #pragma unroll
            for (int i = 0; i < 4; i++) qv[i] = Qs[(ty * 4 + i) * 64 + d];
            #pragma unroll
            for (int j = 0; j < 4; j++) kv[j] = Ks[(tx * 4 + j) * 65 + d];
            #pragma unroll
            for (int i = 0; i < 4; i++)
                #pragma unroll
                for (int j = 0; j < 4; j++)
                    s[i][j] = fmaf(qv[i], kv[j], s[i][j]);
        }

        // scale + decay + causal mask (diag tile only)
        #pragma unroll
        for (int i = 0; i < 4; i++)
            #pragma unroll
            for (int j = 0; j < 4; j++) {
                float val = s[i][j] * 0.125f - cj[j];
                if (kt == qt && (tx * 4 + j) > (ty * 4 + i)) val = -1e30f;
                s[i][j] = val;
            }

        // online softmax: row max / sum across the 16 tx lanes
        float mnew[4], sc[4];
        #pragma unroll
        for (int i = 0; i < 4; i++) {
            float mt = fmaxf(fmaxf(s[i][0], s[i][1]), fmaxf(s[i][2], s[i][3]));
            #pragma unroll
            for (int off = 8; off > 0; off >>= 1)
                mt = fmaxf(mt, __shfl_xor_sync(0xffffffffu, mt, off));
            mnew[i] = fmaxf(m[i], mt);
            sc[i] = __expf(m[i] - mnew[i]);
            m[i] = mnew[i];
        }
        #pragma unroll
        for (int i = 0; i < 4; i++) {
            float rs = 0.f;
            #pragma unroll
            for (int j = 0; j < 4; j++) {
                float p = __expf(s[i][j] - mnew[i]);
                s[i][j] = p;
                rs += p;
            }
            #pragma unroll
            for (int off = 8; off > 0; off >>= 1)
                rs += __shfl_xor_sync(0xffffffffu, rs, off);
            l[i] = l[i] * sc[i] + rs;
            #pragma unroll
            for (int j = 0; j < 4; j++) acc[i][j] *= sc[i];
        }

        // stage P in smem, then O += P @ V
        #pragma unroll
        for (int i = 0; i < 4; i++)
            #pragma unroll
            for (int j = 0; j < 4; j++)
                Ps[(ty * 4 + i) * 65 + tx * 4 + j] = s[i][j];
        __syncthreads();

        #pragma unroll 8
        for (int kk = 0; kk < 64; kk++) {
            float4 vv = *(const float4*)(Vs + kk * 64 + tx * 4);
            #pragma unroll
            for (int i = 0; i < 4; i++) {
                float p = Ps[(ty * 4 + i) * 65 + kk];
                acc[i][0] = fmaf(p, vv.x, acc[i][0]);
                acc[i][1] = fmaf(p, vv.y, acc[i][1]);
                acc[i][2] = fmaf(p, vv.z, acc[i][2]);
                acc[i][3] = fmaf(p, vv.w, acc[i][3]);
            }
        }
        __syncthreads();
    }

    #pragma unroll
    for (int i = 0; i < 4; i++) {
        float inv = 1.0f / l[i];
        float4 o = make_float4(acc[i][0] * inv, acc[i][1] * inv,
                               acc[i][2] * inv, acc[i][3] * inv);
        *(float4*)(Out + (rowbase + qbase + ty * 4 + i) * D_MODEL +
                   h * D_HEAD + tx * 4) = o;
    }
}

// ---------------- launcher ----------------
extern "C" void kernel_launch(void* const* d_in, const int* in_sizes, int n_in,
                              void* d_out, int out_size)
{
    const float* x    = (const float*)d_in[0];
    const float* ln1g = (const float*)d_in[1];
    const float* ln1b = (const float*)d_in[2];
    const float* wq   = (const float*)d_in[3];
    const float* bq   = (const float*)d_in[4];
    const float* wk   = (const float*)d_in[5];
    const float* bk   = (const float*)d_in[6];
    const float* wv   = (const float*)d_in[7];
    const float* bv   = (const float*)d_in[8];
    const float* wo   = (const float*)d_in[9];
    const float* bo   = (const float*)d_in[10];
    const float* wf   = (const float*)d_in[11];
    const float* bf   = (const float*)d_in[12];
    const float* ln2g = (const float*)d_in[13];
    const float* ln2b = (const float*)d_in[14];
    const float* w1   = (const float*)d_in[15];
    const float* b1   = (const float*)d_in[16];
    const float* w2   = (const float*)d_in[17];
    const float* b2   = (const float*)d_in[18];
    float* out = (float*)d_out;

    float *h, *q, *k, *v, *c, *ctx, *x1, *h2, *ff;
    cudaGetSymbolAddress((void**)&h,   g_h);
    cudaGetSymbolAddress((void**)&q,   g_q);
    cudaGetSymbolAddress((void**)&k,   g_k);
    cudaGetSymbolAddress((void**)&v,   g_v);
    cudaGetSymbolAddress((void**)&c,   g_c);
    cudaGetSymbolAddress((void**)&ctx, g_ctx);
    cudaGetSymbolAddress((void**)&x1,  g_x1);
    cudaGetSymbolAddress((void**)&h2,  g_h2);
    cudaGetSymbolAddress((void**)&ff,  g_ff);

    // 1) LN1
    ln_kernel<<<NTOK, 256>>>(x, ln1g, ln1b, h);
    // 2-4) Q, K, V projections
    gemm64<<<dim3(D_MODEL/64, NTOK/64), 256>>>(h, wq, bq, nullptr, q, NTOK, D_MODEL, D_MODEL, 0);
    gemm64<<<dim3(D_MODEL/64, NTOK/64), 256>>>(h, wk, bk, nullptr, k, NTOK, D_MODEL, D_MODEL, 0);
    gemm64<<<dim3(D_MODEL/64, NTOK/64), 256>>>(h, wv, bv, nullptr, v, NTOK, D_MODEL, D_MODEL, 0);
    // 5) forget gate logits + 6) cumulative log-decay
    fgate_kernel<<<NTOK, 256>>>(h, wf, bf, c);
    cumsum_kernel<<<BATCH * N_HEADS, 256>>>(c);
    // 7) attention
    int smem = (64*64 + 64*65 + 64*64 + 64*65) * (int)sizeof(float);
    cudaFuncSetAttribute(attn_kernel, cudaFuncAttributeMaxDynamicSharedMemorySize, smem);
    attn_kernel<<<dim3(SEQ/64, N_HEADS, BATCH), 256, smem>>>(q, k, v, c, ctx);
    // 8) output proj + residual
    gemm64<<<dim3(D_MODEL/64, NTOK/64), 256>>>(ctx, wo, bo, x, x1, NTOK, D_MODEL, D_MODEL, 0);
    // 9) LN2
    ln_kernel<<<NTOK, 256>>>(x1, ln2g, ln2b, h2);
    // 10) FF up + GELU
    gemm64<<<dim3(D_FF/64, NTOK/64), 256>>>(h2, w1, b1, nullptr, ff, NTOK, D_FF, D_MODEL, 1);
    // 11) FF down + residual -> output
    gemm64<<<dim3(D_MODEL/64, NTOK/64), 256>>>(ff, w2, b2, x1, out, NTOK, D_MODEL, D_FF, 0);
}

// round 2
// speedup vs baseline: 2.5607x; 2.5607x over previous
#include <cuda_runtime.h>
#include <math.h>
#include <stdint.h>

#define D_MODEL 1024
#define N_HEADS 16
#define D_HEAD  64
#define D_FF    4096
#define BATCH   2
#define SEQ     2048
#define NTOK    (BATCH*SEQ)

// ---------------- scratch (no cudaMalloc allowed) ----------------
__device__ float g_h  [NTOK*D_MODEL];
__device__ float g_q  [NTOK*D_MODEL];
__device__ float g_k  [NTOK*D_MODEL];
__device__ float g_v  [NTOK*D_MODEL];
__device__ float g_c  [NTOK*N_HEADS];
__device__ float g_ctx[NTOK*D_MODEL];
__device__ float g_x1 [NTOK*D_MODEL];
__device__ float g_h2 [NTOK*D_MODEL];
__device__ float g_ff [NTOK*D_FF];

// ---------------- LayerNorm: one block per token row ----------------
__global__ __launch_bounds__(256) void ln_kernel(
    const float* __restrict__ x, const float* __restrict__ g,
    const float* __restrict__ b, float* __restrict__ out)
{
    int row = blockIdx.x;
    int tid = threadIdx.x;
    const float4* xr = (const float4*)(x + (size_t)row * D_MODEL);
    float4 v = xr[tid];
    float s  = v.x + v.y + v.z + v.w;
    float s2 = v.x*v.x + v.y*v.y + v.z*v.z + v.w*v.w;

    __shared__ float red[18];
    #pragma unroll
    for (int off = 16; off > 0; off >>= 1) {
        s  += __shfl_xor_sync(0xffffffffu, s,  off);
        s2 += __shfl_xor_sync(0xffffffffu, s2, off);
    }
    int w = tid >> 5, lane = tid & 31;
    if (lane == 0) { red[w] = s; red[8 + w] = s2; }
    __syncthreads();
    if (tid == 0) {
        float a = 0.f, c2 = 0.f;
        #pragma unroll
        for (int i = 0; i < 8; i++) { a += red[i]; c2 += red[8 + i]; }
        red[16] = a; red[17] = c2;
    }
    __syncthreads();
    float mu  = red[16] * (1.0f / D_MODEL);
    float var = red[17] * (1.0f / D_MODEL) - mu * mu;
    float inv = rsqrtf(var + 1e-5f);

    float4 gg = ((const float4*)g)[tid];
    float4 bb = ((const float4*)b)[tid];
    float4 o;
    o.x = (v.x - mu) * inv * gg.x + bb.x;
    o.y = (v.y - mu) * inv * gg.y + bb.y;
    o.z = (v.z - mu) * inv * gg.z + bb.z;
    o.w = (v.w - mu) * inv * gg.w + bb.w;
    ((float4*)(out + (size_t)row * D_MODEL))[tid] = o;
}

// ---------------- TF32 tensor-core GEMM ----------------
// C = act(A @ W + bias) (+resid). A[M,K], W[K,N] row-major.
// CTA tile 128x128, K-chunk 32, 8 warps (2m x 4n), warp tile 64x32.
// mma.sync.m16n8k8.tf32 ; A frags via ldmatrix.x4 ; B frags scalar LDS.
#define BM 128
#define BN 128
#define BK 32
#define AST 36    // As row stride (floats): 9 x 16B groups, odd -> conflict-free ldsm
#define BST 136   // Bs row stride (floats): k-stride mod 32 = 8 -> conflict-free frag LDS

__device__ __forceinline__ uint32_t f2tf32(float x) {
    uint32_t r;
    asm("cvt.rna.tf32.f32 %0, %1;" : "=r"(r) : "f"(x));
    return r;
}

__device__ __forceinline__ float gelu_exact(float x) {
    return 0.5f * x * (1.0f + erff(x * 0.70710678118654752f));
}

__global__ __launch_bounds__(256) void gemm_tc(
    const float* __restrict__ A, const float* __restrict__ W,
    const float* __restrict__ bias, const float* __restrict__ resid,
    float* __restrict__ C, int M, int N, int K, int act)
{
    __shared__ uint32_t As[BM * AST];
    __shared__ uint32_t Bs[BK * BST];

    int tid  = threadIdx.x;
    int wid  = tid >> 5, lane = tid & 31;
    int warp_m = wid >> 2;      // 0..1
    int warp_n = wid & 3;       // 0..3
    int gid = lane >> 2, tig = lane & 3;
    int mb = blockIdx.y * BM, nb = blockIdx.x * BN;

    float acc[4][4][4];
    #pragma unroll
    for (int mt = 0; mt < 4; mt++)
        #pragma unroll
        for (int nt = 0; nt < 4; nt++)
            #pragma unroll
            for (int r = 0; r < 4; r++) acc[mt][nt][r] = 0.f;

    // A-load mapping: idx -> (m, kg) with kg permuted so STS phases are conflict-free
    int a_m[4], a_kg[4];
    const float* a_gp[4];
    #pragma unroll
    for (int i = 0; i < 4; i++) {
        int idx = tid + i * 256;            // 0..1023
        int m = idx >> 3;                   // 0..127
        int kgr = idx & 7;
        int kg = (kgr + 8 - (m & 7)) & 7;   // permute: store-phase banks distinct
        a_m[i] = m; a_kg[i] = kg;
        a_gp[i] = A + (size_t)(mb + m) * K + kg * 4;
    }
    // B-load mapping: idx -> (k, ng)
    int b_k[4], b_ng[4];
    const float* b_gp[4];
    #pragma unroll
    for (int i = 0; i < 4; i++) {
        int idx = tid + i * 256;
        int k = idx >> 5, ng = idx & 31;
        b_k[i] = k; b_ng[i] = ng;
        b_gp[i] = W + (size_t)k * N + nb + ng * 4;
    }

    // ldmatrix source rows for this lane
    int lm_row = ((lane >> 3) & 1) * 8 + (lane & 7);  // row offset within 16-row tile
    int lm_khalf = (lane >> 4);                        // 0: k 0..3, 1: k 4..7

    for (int k0 = 0; k0 < K; k0 += BK) {
        // global -> smem (with tf32 conversion)
        #pragma unroll
        for (int i = 0; i < 4; i++) {
            float4 av = *(const float4*)(a_gp[i] + k0);
            uint32_t* d = &As[a_m[i] * AST + a_kg[i] * 4];
            d[0] = f2tf32(av.x); d[1] = f2tf32(av.y);
            d[2] = f2tf32(av.z); d[3] = f2tf32(av.w);
        }
        #pragma unroll
        for (int i = 0; i < 4; i++) {
            float4 wv = *(const float4*)(b_gp[i] + (size_t)k0 * N);
            uint32_t* d = &Bs[b_k[i] * BST + b_ng[i] * 4];
            d[0] = f2tf32(wv.x); d[1] = f2tf32(wv.y);
            d[2] = f2tf32(wv.z); d[3] = f2tf32(wv.w);
        }
        __syncthreads();

        #pragma unroll
        for (int ks = 0; ks < 4; ks++) {
            uint32_t af[4][4];
            #pragma unroll
            for (int mt = 0; mt < 4; mt++) {
                int row = warp_m * 64 + mt * 16 + lm_row;
                int kg  = ks * 2 + lm_khalf;
                uint32_t saddr = (uint32_t)__cvta_generic_to_shared(
                    &As[row * AST + kg * 4]);
                asm volatile(
                    "ldmatrix.sync.aligned.m8n8.x4.shared.b16 {%0,%1,%2,%3}, [%4];"
                    : "=r"(af[mt][0]), "=r"(af[mt][1]),
                      "=r"(af[mt][2]), "=r"(af[mt][3])
                    : "r"(saddr));
            }
            uint32_t bf[4][2];
            #pragma unroll
            for (int nt = 0; nt < 4; nt++) {
                int n0 = warp_n * 32 + nt * 8 + gid;
                bf[nt][0] = Bs[(ks * 8 + tig)     * BST + n0];
                bf[nt][1] = Bs[(ks * 8 + tig + 4) * BST + n0];
            }
            #pragma unroll
            for (int mt = 0; mt < 4; mt++)
                #pragma unroll
                for (int nt = 0; nt < 4; nt++) {
                    asm volatile(
                        "mma.sync.aligned.m16n8k8.row.col.f32.tf32.tf32.f32 "
                        "{%0,%1,%2,%3}, {%4,%5,%6,%7}, {%8,%9}, {%0,%1,%2,%3};"
                        : "+f"(acc[mt][nt][0]), "+f"(acc[mt][nt][1]),
                          "+f"(acc[mt][nt][2]), "+f"(acc[mt][nt][3])
                        : "r"(af[mt][0]), "r"(af[mt][1]),
                          "r"(af[mt][2]), "r"(af[mt][3]),
                          "r"(bf[nt][0]), "r"(bf[nt][1]));
                }
        }
        __syncthreads();
    }

    // epilogue
    #pragma unroll
    for (int mt = 0; mt < 4; mt++) {
        int r0 = mb + warp_m * 64 + mt * 16 + gid;
        int r1 = r0 + 8;
        #pragma unroll
        for (int nt = 0; nt < 4; nt++) {
            int cc = nb + warp_n * 32 + nt * 8 + tig * 2;
            float b0 = bias[cc], b1 = bias[cc + 1];
            float v00 = acc[mt][nt][0] + b0, v01 = acc[mt][nt][1] + b1;
            float v10 = acc[mt][nt][2] + b0, v11 = acc[mt][nt][3] + b1;
            if (act == 1) {
                v00 = gelu_exact(v00); v01 = gelu_exact(v01);
                v10 = gelu_exact(v10); v11 = gelu_exact(v11);
            }
            size_t p0 = (size_t)r0 * N + cc;
            size_t p1 = (size_t)r1 * N + cc;
            if (resid) {
                float2 q0 = *(const float2*)(resid + p0);
                float2 q1 = *(const float2*)(resid + p1);
                v00 += q0.x; v01 += q0.y; v10 += q1.x; v11 += q1.y;
            }
            *(float2*)(C + p0) = make_float2(v00, v01);
            *(float2*)(C + p1) = make_float2(v10, v11);
        }
    }
}

// ---------------- forget gate: logf = log_sigmoid(h @ wf + bf) ----------------
__global__ __launch_bounds__(256) void fgate_kernel(
    const float* __restrict__ h, const float* __restrict__ wf,
    const float* __restrict__ bf, float* __restrict__ logf)
{
    int t   = blockIdx.x;
    int tid = threadIdx.x;
    int hd  = tid >> 4;
    int ln  = tid & 15;
    const float* hr = h + (size_t)t * D_MODEL;
    float s = 0.f;
    #pragma unroll 8
    for (int k = ln; k < D_MODEL; k += 16)
        s = fmaf(hr[k], wf[(size_t)k * N_HEADS + hd], s);
    #pragma unroll
    for (int off = 8; off > 0; off >>= 1)
        s += __shfl_xor_sync(0xffffffffu, s, off);
    if (ln == 0) {
        float z = s + bf[hd];
        float ls = (z >= 0.f) ? -log1pf(expf(-z)) : (z - log1pf(expf(z)));
        logf[(size_t)t * N_HEADS + hd] = ls;
    }
}

// ---------------- in-place cumsum over sequence per (b,h) ----------------
__global__ __launch_bounds__(256) void cumsum_kernel(float* __restrict__ c)
{
    int bh = blockIdx.x;
    int b  = bh >> 4, h = bh & 15;
    int tid = threadIdx.x;
    const int CHUNK = SEQ / 256;
    float vals[CHUNK];
    float run = 0.f;
    size_t base = (size_t)b * SEQ * N_HEADS + h;
    #pragma unroll
    for (int u = 0; u < CHUNK; u++) {
        run += c[base + (size_t)(tid * CHUNK + u) * N_HEADS];
        vals[u] = run;
    }
    __shared__ float tot[256];
    tot[tid] = run;
    __syncthreads();
    for (int off = 1; off < 256; off <<= 1) {
        float t = (tid >= off) ? tot[tid - off] : 0.f;
        __syncthreads();
        tot[tid] += t;
        __syncthreads();
    }
    float offs = tot[tid] - run;
    #pragma unroll
    for (int u = 0; u < CHUNK; u++)
        c[base + (size_t)(tid * CHUNK + u) * N_HEADS] = vals[u] + offs;
}

// ---------------- flash attention with forgetting decay ----------------
__global__ __launch_bounds__(256) void attn_kernel(
    const float* __restrict__ Q, const float* __restrict__ Kp,
    const float* __restrict__ Vp, const float* __restrict__ Cdec,
    float* __restrict__ Out)
{
    extern __shared__ float sm[];
    float* Qs = sm;
    float* Ks = Qs + 64 * 64;
    float* Vs = Ks + 64 * 65;
    float* Ps = Vs + 64 * 64;

    int qt = blockIdx.x, h = blockIdx.y, b = blockIdx.z;
    int tid = threadIdx.x;
    int tx = tid & 15, ty = tid >> 4;
    int qbase = qt * 64;
    size_t rowbase = (size_t)b * SEQ;

    const float* qg = Q + (rowbase + qbase) * D_MODEL + h * D_HEAD;
    #pragma unroll
    for (int i = 0; i < 4; i++) {
        int e = tid + i * 256;
        int r = e >> 4, d4 = e & 15;
        *(float4*)(Qs + r * 64 + d4 * 4) =
            *(const float4*)(qg + (size_t)r * D_MODEL + d4 * 4);
    }

    float m[4], l[4], acc[4][4];
    #pragma unroll
    for (int i = 0; i < 4; i++) {
        m[i] = -1e30f; l[i] = 0.f;
        #pragma unroll
        for (int j = 0; j < 4; j++) acc[i][j] = 0.f;
    }
    __syncthreads();

    for (int kt = 0; kt <= qt; kt++) {
        int kbase = kt * 64;
        const float* kg = Kp + (rowbase + kbase) * D_MODEL + h * D_HEAD;
        const float* vg = Vp + (rowbase + kbase) * D_MODEL + h * D_HEAD;
        #pragma unroll
        for (int i = 0; i < 4; i++) {
            int e = tid + i * 256;
            int r = e >> 4, d4 = e & 15;
            float4 kv = *(const float4*)(kg + (size_t)r * D_MODEL + d4 * 4);
            float* kd = Ks + r * 65 + d4 * 4;
            kd[0] = kv.x; kd[1] = kv.y; kd[2] = kv.z; kd[3] = kv.w;
            *(float4*)(Vs + r * 64 + d4 * 4) =
                *(const float4*)(vg + (size_t)r * D_MODEL + d4 * 4);
        }
        float cj[4];
        #pragma unroll
        for (int j = 0; j < 4; j++)
            cj[j] = Cdec[(rowbase + kbase + tx * 4 + j) * N_HEADS + h];
        __syncthreads();

        float s[4][4] = {};
        #pragma unroll 8
        for (int d = 0; d < 64; d++) {
            float qv[4], kv[4];
            #pragma unroll
            for (int i = 0; i < 4; i++) qv[i] = Qs[(ty * 4 + i) * 64 + d];
            #pragma unroll
            for (int j = 0; j < 4; j++) kv[j] = Ks[(tx * 4 + j) * 65 + d];
            #pragma unroll
            for (int i = 0; i < 4; i++)
                #pragma unroll
                for (int j = 0; j < 4; j++)
                    s[i][j] = fmaf(qv[i], kv[j], s[i][j]);
        }

        #pragma unroll
        for (int i = 0; i < 4; i++)
            #pragma unroll
            for (int j = 0; j < 4; j++) {
                float val = s[i][j] * 0.125f - cj[j];
                if (kt == qt && (tx * 4 + j) > (ty * 4 + i)) val = -1e30f;
                s[i][j] = val;
            }

        float mnew[4], sc[4];
        #pragma unroll
        for (int i = 0; i < 4; i++) {
            float mt = fmaxf(fmaxf(s[i][0], s[i][1]), fmaxf(s[i][2], s[i][3]));
            #pragma unroll
            for (int off = 8; off > 0; off >>= 1)
                mt = fmaxf(mt, __shfl_xor_sync(0xffffffffu, mt, off));
            mnew[i] = fmaxf(m[i], mt);
            sc[i] = __expf(m[i] - mnew[i]);
            m[i] = mnew[i];
        }
        #pragma unroll
        for (int i = 0; i < 4; i++) {
            float rs = 0.f;
            #pragma unroll
            for (int j = 0; j < 4; j++) {
                float p = __expf(s[i][j] - mnew[i]);
                s[i][j] = p;
                rs += p;
            }
            #pragma unroll
            for (int off = 8; off > 0; off >>= 1)
                rs += __shfl_xor_sync(0xffffffffu, rs, off);
            l[i] = l[i] * sc[i] + rs;
            #pragma unroll
            for (int j = 0; j < 4; j++) acc[i][j] *= sc[i];
        }

        #pragma unroll
        for (int i = 0; i < 4; i++)
            #pragma unroll
            for (int j = 0; j < 4; j++)
                Ps[(ty * 4 + i) * 65 + tx * 4 + j] = s[i][j];
        __syncthreads();

        #pragma unroll 8
        for (int kk = 0; kk < 64; kk++) {
            float4 vv = *(const float4*)(Vs + kk * 64 + tx * 4);
            #pragma unroll
            for (int i = 0; i < 4; i++) {
                float p = Ps[(ty * 4 + i) * 65 + kk];
                acc[i][0] = fmaf(p, vv.x, acc[i][0]);
                acc[i][1] = fmaf(p, vv.y, acc[i][1]);
                acc[i][2] = fmaf(p, vv.z, acc[i][2]);
                acc[i][3] = fmaf(p, vv.w, acc[i][3]);
            }
        }
        __syncthreads();
    }

    #pragma unroll
    for (int i = 0; i < 4; i++) {
        float inv = 1.0f / l[i];
        float4 o = make_float4(acc[i][0] * inv, acc[i][1] * inv,
                               acc[i][2] * inv, acc[i][3] * inv);
        *(float4*)(Out + (rowbase + qbase + ty * 4 + i) * D_MODEL +
                   h * D_HEAD + tx * 4) = o;
    }
}

// ---------------- launcher ----------------
extern "C" void kernel_launch(void* const* d_in, const int* in_sizes, int n_in,
                              void* d_out, int out_size)
{
    const float* x    = (const float*)d_in[0];
    const float* ln1g = (const float*)d_in[1];
    const float* ln1b = (const float*)d_in[2];
    const float* wq   = (const float*)d_in[3];
    const float* bq   = (const float*)d_in[4];
    const float* wk   = (const float*)d_in[5];
    const float* bk   = (const float*)d_in[6];
    const float* wv   = (const float*)d_in[7];
    const float* bv   = (const float*)d_in[8];
    const float* wo   = (const float*)d_in[9];
    const float* bo   = (const float*)d_in[10];
    const float* wf   = (const float*)d_in[11];
    const float* bf   = (const float*)d_in[12];
    const float* ln2g = (const float*)d_in[13];
    const float* ln2b = (const float*)d_in[14];
    const float* w1   = (const float*)d_in[15];
    const float* b1   = (const float*)d_in[16];
    const float* w2   = (const float*)d_in[17];
    const float* b2   = (const float*)d_in[18];
    float* out = (float*)d_out;

    float *h, *q, *k, *v, *c, *ctx, *x1, *h2, *ff;
    cudaGetSymbolAddress((void**)&h,   g_h);
    cudaGetSymbolAddress((void**)&q,   g_q);
    cudaGetSymbolAddress((void**)&k,   g_k);
    cudaGetSymbolAddress((void**)&v,   g_v);
    cudaGetSymbolAddress((void**)&c,   g_c);
    cudaGetSymbolAddress((void**)&ctx, g_ctx);
    cudaGetSymbolAddress((void**)&x1,  g_x1);
    cudaGetSymbolAddress((void**)&h2,  g_h2);
    cudaGetSymbolAddress((void**)&ff,  g_ff);

    // 1) LN1
    ln_kernel<<<NTOK, 256>>>(x, ln1g, ln1b, h);
    // 2-4) Q, K, V projections (tensor cores)
    gemm_tc<<<dim3(D_MODEL/BN, NTOK/BM), 256>>>(h, wq, bq, nullptr, q, NTOK, D_MODEL, D_MODEL, 0);
    gemm_tc<<<dim3(D_MODEL/BN, NTOK/BM), 256>>>(h, wk, bk, nullptr, k, NTOK, D_MODEL, D_MODEL, 0);
    gemm_tc<<<dim3(D_MODEL/BN, NTOK/BM), 256>>>(h, wv, bv, nullptr, v, NTOK, D_MODEL, D_MODEL, 0);
    // 5) forget gate + 6) cumulative log-decay
    fgate_kernel<<<NTOK, 256>>>(h, wf, bf, c);
    cumsum_kernel<<<BATCH * N_HEADS, 256>>>(c);
    // 7) attention
    int smem = (64*64 + 64*65 + 64*64 + 64*65) * (int)sizeof(float);
    cudaFuncSetAttribute(attn_kernel, cudaFuncAttributeMaxDynamicSharedMemorySize, smem);
    attn_kernel<<<dim3(SEQ/64, N_HEADS, BATCH), 256, smem>>>(q, k, v, c, ctx);
    // 8) output proj + residual
    gemm_tc<<<dim3(D_MODEL/BN, NTOK/BM), 256>>>(ctx, wo, bo, x, x1, NTOK, D_MODEL, D_MODEL, 0);
    // 9) LN2
    ln_kernel<<<NTOK, 256>>>(x1, ln2g, ln2b, h2);
    // 10) FF up + GELU
    gemm_tc<<<dim3(D_FF/BN, NTOK/BM), 256>>>(h2, w1, b1, nullptr, ff, NTOK, D_FF, D_MODEL, 1);
    // 11) FF down + residual -> output
    gemm_tc<<<dim3(D_MODEL/BN, NTOK/BM), 256>>>(ff, w2, b2, x1, out, NTOK, D_MODEL, D_FF, 0);
}

// round 3
// speedup vs baseline: 3.3745x; 1.3178x over previous
#include <cuda_runtime.h>
#include <math.h>
#include <stdint.h>

#define D_MODEL 1024
#define N_HEADS 16
#define D_HEAD  64
#define D_FF    4096
#define BATCH   2
#define SEQ     2048
#define NTOK    (BATCH*SEQ)

// ---------------- scratch (no cudaMalloc allowed) ----------------
__device__ float g_h  [NTOK*D_MODEL];
__device__ float g_q  [NTOK*D_MODEL];
__device__ float g_k  [NTOK*D_MODEL];
__device__ float g_v  [NTOK*D_MODEL];
__device__ float g_c  [NTOK*N_HEADS];
__device__ float g_ctx[NTOK*D_MODEL];
__device__ float g_x1 [NTOK*D_MODEL];
__device__ float g_h2 [NTOK*D_MODEL];
__device__ float g_ff [NTOK*D_FF];

__device__ __forceinline__ uint32_t f2tf32(float x) {
    uint32_t r;
    asm("cvt.rna.tf32.f32 %0, %1;" : "=r"(r) : "f"(x));
    return r;
}
__device__ __forceinline__ uint32_t u2tf32(uint32_t x) {
    uint32_t r;
    asm("cvt.rna.tf32.f32 %0, %1;" : "=r"(r) : "f"(__uint_as_float(x)));
    return r;
}
__device__ __forceinline__ void cp16(uint32_t dst, const void* src) {
    asm volatile("cp.async.cg.shared.global [%0], [%1], 16;" :: "r"(dst), "l"(src));
}
#define CP_COMMIT() asm volatile("cp.async.commit_group;")
#define CP_WAIT0()  asm volatile("cp.async.wait_group 0;")

__device__ __forceinline__ void mma_tf32(float* c, const uint32_t* a,
                                         uint32_t b0, uint32_t b1) {
    asm volatile(
        "mma.sync.aligned.m16n8k8.row.col.f32.tf32.tf32.f32 "
        "{%0,%1,%2,%3}, {%4,%5,%6,%7}, {%8,%9}, {%0,%1,%2,%3};"
        : "+f"(c[0]), "+f"(c[1]), "+f"(c[2]), "+f"(c[3])
        : "r"(a[0]), "r"(a[1]), "r"(a[2]), "r"(a[3]), "r"(b0), "r"(b1));
}

__device__ __forceinline__ float gelu_exact(float x) {
    return 0.5f * x * (1.0f + erff(x * 0.70710678118654752f));
}

// ---------------- LayerNorm: one block per token row ----------------
__global__ __launch_bounds__(256) void ln_kernel(
    const float* __restrict__ x, const float* __restrict__ g,
    const float* __restrict__ b, float* __restrict__ out)
{
    int row = blockIdx.x;
    int tid = threadIdx.x;
    const float4* xr = (const float4*)(x + (size_t)row * D_MODEL);
    float4 v = xr[tid];
    float s  = v.x + v.y + v.z + v.w;
    float s2 = v.x*v.x + v.y*v.y + v.z*v.z + v.w*v.w;

    __shared__ float red[18];
    #pragma unroll
    for (int off = 16; off > 0; off >>= 1) {
        s  += __shfl_xor_sync(0xffffffffu, s,  off);
        s2 += __shfl_xor_sync(0xffffffffu, s2, off);
    }
    int w = tid >> 5, lane = tid & 31;
    if (lane == 0) { red[w] = s; red[8 + w] = s2; }
    __syncthreads();
    if (tid == 0) {
        float a = 0.f, c2 = 0.f;
        #pragma unroll
        for (int i = 0; i < 8; i++) { a += red[i]; c2 += red[8 + i]; }
        red[16] = a; red[17] = c2;
    }
    __syncthreads();
    float mu  = red[16] * (1.0f / D_MODEL);
    float var = red[17] * (1.0f / D_MODEL) - mu * mu;
    float inv = rsqrtf(var + 1e-5f);

    float4 gg = ((const float4*)g)[tid];
    float4 bb = ((const float4*)b)[tid];
    float4 o;
    o.x = (v.x - mu) * inv * gg.x + bb.x;
    o.y = (v.y - mu) * inv * gg.y + bb.y;
    o.z = (v.z - mu) * inv * gg.z + bb.z;
    o.w = (v.w - mu) * inv * gg.w + bb.w;
    ((float4*)(out + (size_t)row * D_MODEL))[tid] = o;
}

// ---------------- TF32 tensor-core GEMM, cp.async double-buffered ----------------
#define BM 128
#define BN 128
#define BK 32
#define AST 36
#define BST 136
#define ASZ (BM*AST)
#define BSZ (BK*BST)
#define GEMM_SMEM ((2*ASZ + 2*BSZ) * 4)

__global__ __launch_bounds__(256) void gemm_tc(
    const float* __restrict__ A, const float* __restrict__ W,
    const float* __restrict__ bias, const float* __restrict__ resid,
    float* __restrict__ C, int M, int N, int K, int act)
{
    extern __shared__ uint32_t dsm[];
    uint32_t* As = dsm;            // 2 x [BM][AST] raw fp32
    uint32_t* Bs = dsm + 2*ASZ;    // 2 x [BK][BST] raw fp32

    int tid  = threadIdx.x;
    int wid  = tid >> 5, lane = tid & 31;
    int warp_m = wid >> 2;
    int warp_n = wid & 3;
    int gid = lane >> 2, tig = lane & 3;
    int mb = blockIdx.y * BM, nb = blockIdx.x * BN;

    float acc[4][4][4];
    #pragma unroll
    for (int mt = 0; mt < 4; mt++)
        #pragma unroll
        for (int nt = 0; nt < 4; nt++)
            #pragma unroll
            for (int r = 0; r < 4; r++) acc[mt][nt][r] = 0.f;

    // A-load mapping (permuted kg for conflict-free store phases)
    const float* a_gp[4];
    uint32_t a_dst[4];
    #pragma unroll
    for (int i = 0; i < 4; i++) {
        int idx = tid + i * 256;
        int m = idx >> 3;
        int kg = ((idx & 7) + 8 - (m & 7)) & 7;
        a_gp[i] = A + (size_t)(mb + m) * K + kg * 4;
        a_dst[i] = (uint32_t)__cvta_generic_to_shared(&As[m * AST + kg * 4]);
    }
    // B-load mapping
    const float* b_gp[4];
    uint32_t b_dst[4];
    #pragma unroll
    for (int i = 0; i < 4; i++) {
        int idx = tid + i * 256;
        int k = idx >> 5, ng = idx & 31;
        b_gp[i] = W + (size_t)k * N + nb + ng * 4;
        b_dst[i] = (uint32_t)__cvta_generic_to_shared(&Bs[k * BST + ng * 4]);
    }

    int lm_row = ((lane >> 3) & 1) * 8 + (lane & 7);
    int lm_khalf = (lane >> 4);

    // prologue: prefetch chunk 0 into buffer 0
    #pragma unroll
    for (int i = 0; i < 4; i++) cp16(a_dst[i], a_gp[i]);
    #pragma unroll
    for (int i = 0; i < 4; i++) cp16(b_dst[i], b_gp[i]);
    CP_COMMIT();

    int buf = 0;
    for (int k0 = 0; k0 < K; k0 += BK) {
        CP_WAIT0();
        __syncthreads();
        if (k0 + BK < K) {
            int nb_ofs = (buf ^ 1);
            #pragma unroll
            for (int i = 0; i < 4; i++)
                cp16(a_dst[i] + nb_ofs * ASZ * 4, a_gp[i] + k0 + BK);
            #pragma unroll
            for (int i = 0; i < 4; i++)
                cp16(b_dst[i] + nb_ofs * BSZ * 4, b_gp[i] + (size_t)(k0 + BK) * N);
            CP_COMMIT();
        }

        const uint32_t* Ab = As + buf * ASZ;
        const uint32_t* Bb = Bs + buf * BSZ;
        #pragma unroll
        for (int ks = 0; ks < 4; ks++) {
            uint32_t af[4][4];
            #pragma unroll
            for (int mt = 0; mt < 4; mt++) {
                int row = warp_m * 64 + mt * 16 + lm_row;
                int kg  = ks * 2 + lm_khalf;
                uint32_t saddr = (uint32_t)__cvta_generic_to_shared(
                    &Ab[row * AST + kg * 4]);
                asm volatile(
                    "ldmatrix.sync.aligned.m8n8.x4.shared.b16 {%0,%1,%2,%3}, [%4];"
                    : "=r"(af[mt][0]), "=r"(af[mt][1]),
                      "=r"(af[mt][2]), "=r"(af[mt][3])
                    : "r"(saddr));
                #pragma unroll
                for (int r = 0; r < 4; r++) af[mt][r] = u2tf32(af[mt][r]);
            }
            uint32_t bf[4][2];
            #pragma unroll
            for (int nt = 0; nt < 4; nt++) {
                int n0 = warp_n * 32 + nt * 8 + gid;
                bf[nt][0] = u2tf32(Bb[(ks * 8 + tig)     * BST + n0]);
                bf[nt][1] = u2tf32(Bb[(ks * 8 + tig + 4) * BST + n0]);
            }
            #pragma unroll
            for (int mt = 0; mt < 4; mt++)
                #pragma unroll
                for (int nt = 0; nt < 4; nt++)
                    mma_tf32(acc[mt][nt], af[mt], bf[nt][0], bf[nt][1]);
        }
        buf ^= 1;
    }

    // epilogue
    #pragma unroll
    for (int mt = 0; mt < 4; mt++) {
        int r0 = mb + warp_m * 64 + mt * 16 + gid;
        int r1 = r0 + 8;
        #pragma unroll
        for (int nt = 0; nt < 4; nt++) {
            int cc = nb + warp_n * 32 + nt * 8 + tig * 2;
            float b0 = bias[cc], b1 = bias[cc + 1];
            float v00 = acc[mt][nt][0] + b0, v01 = acc[mt][nt][1] + b1;
            float v10 = acc[mt][nt][2] + b0, v11 = acc[mt][nt][3] + b1;
            if (act == 1) {
                v00 = gelu_exact(v00); v01 = gelu_exact(v01);
                v10 = gelu_exact(v10); v11 = gelu_exact(v11);
            }
            size_t p0 = (size_t)r0 * N + cc;
            size_t p1 = (size_t)r1 * N + cc;
            if (resid) {
                float2 q0 = *(const float2*)(resid + p0);
                float2 q1 = *(const float2*)(resid + p1);
                v00 += q0.x; v01 += q0.y; v10 += q1.x; v11 += q1.y;
            }
            *(float2*)(C + p0) = make_float2(v00, v01);
            *(float2*)(C + p1) = make_float2(v10, v11);
        }
    }
}

// ---------------- forget gate ----------------
__global__ __launch_bounds__(256) void fgate_kernel(
    const float* __restrict__ h, const float* __restrict__ wf,
    const float* __restrict__ bf, float* __restrict__ logf)
{
    int t   = blockIdx.x;
    int tid = threadIdx.x;
    int hd  = tid >> 4;
    int ln  = tid & 15;
    const float* hr = h + (size_t)t * D_MODEL;
    float s = 0.f;
    #pragma unroll 8
    for (int k = ln; k < D_MODEL; k += 16)
        s = fmaf(hr[k], wf[(size_t)k * N_HEADS + hd], s);
    #pragma unroll
    for (int off = 8; off > 0; off >>= 1)
        s += __shfl_xor_sync(0xffffffffu, s, off);
    if (ln == 0) {
        float z = s + bf[hd];
        float ls = (z >= 0.f) ? -log1pf(expf(-z)) : (z - log1pf(expf(z)));
        logf[(size_t)t * N_HEADS + hd] = ls;
    }
}

// ---------------- cumsum per (b,h) ----------------
__global__ __launch_bounds__(256) void cumsum_kernel(float* __restrict__ c)
{
    int bh = blockIdx.x;
    int b  = bh >> 4, h = bh & 15;
    int tid = threadIdx.x;
    const int CHUNK = SEQ / 256;
    float vals[CHUNK];
    float run = 0.f;
    size_t base = (size_t)b * SEQ * N_HEADS + h;
    #pragma unroll
    for (int u = 0; u < CHUNK; u++) {
        run += c[base + (size_t)(tid * CHUNK + u) * N_HEADS];
        vals[u] = run;
    }
    __shared__ float tot[256];
    tot[tid] = run;
    __syncthreads();
    for (int off = 1; off < 256; off <<= 1) {
        float t = (tid >= off) ? tot[tid - off] : 0.f;
        __syncthreads();
        tot[tid] += t;
        __syncthreads();
    }
    float offs = tot[tid] - run;
    #pragma unroll
    for (int u = 0; u < CHUNK; u++)
        c[base + (size_t)(tid * CHUNK + u) * N_HEADS] = vals[u] + offs;
}

// ---------------- tensor-core flash attention with forgetting decay ----------------
// 64 q-rows x 64 k-cols per iteration, 4 warps (16 q-rows each).
// logits = (q.k)/8 - c_j  (c_i row-constant, dropped: softmax invariant)
#define KST 68
#define VST 72
#define PST 68
#define ATTN_SMEM ((64*KST + 64*VST + 64*PST + 64) * 4)

__global__ __launch_bounds__(128) void attn_tc(
    const float* __restrict__ Q, const float* __restrict__ Kp,
    const float* __restrict__ Vp, const float* __restrict__ Cdec,
    float* __restrict__ Out)
{
    extern __shared__ float sm[];
    uint32_t* Ks = (uint32_t*)sm;            // [64][KST] tf32
    uint32_t* Vs = Ks + 64 * KST;            // [64][VST] tf32
    uint32_t* Ps = Vs + 64 * VST;            // [64][PST] tf32 (Q staging, then P)
    float*    cs = (float*)(Ps + 64 * PST);  // [64]

    int qt = blockIdx.x, h = blockIdx.y, b = blockIdx.z;
    int tid = threadIdx.x, wid = tid >> 5, lane = tid & 31;
    int gid = lane >> 2, tig = lane & 3;
    size_t rowbase = (size_t)b * SEQ;
    int qbase = qt * 64;
    int r0 = wid * 16 + gid;   // local row (first of the thread's two rows)

    // stage Q (tf32) into Ps region
    const float* qg = Q + (rowbase + qbase) * D_MODEL + h * D_HEAD;
    #pragma unroll
    for (int i = 0; i < 8; i++) {
        int idx = tid + i * 128;
        int r = idx >> 4, c4 = idx & 15;
        float4 qv = *(const float4*)(qg + (size_t)r * D_MODEL + c4 * 4);
        uint32_t* d = Ps + r * PST + c4 * 4;
        d[0] = f2tf32(qv.x); d[1] = f2tf32(qv.y);
        d[2] = f2tf32(qv.z); d[3] = f2tf32(qv.w);
    }
    __syncthreads();

    // hoist Q fragments to registers (8 k-steps x 4 regs)
    uint32_t qf[8][4];
    #pragma unroll
    for (int ks = 0; ks < 8; ks++) {
        qf[ks][0] = Ps[(r0)     * PST + ks * 8 + tig];
        qf[ks][1] = Ps[(r0 + 8) * PST + ks * 8 + tig];
        qf[ks][2] = Ps[(r0)     * PST + ks * 8 + tig + 4];
        qf[ks][3] = Ps[(r0 + 8) * PST + ks * 8 + tig + 4];
    }

    float oacc[8][4];
    #pragma unroll
    for (int nt = 0; nt < 8; nt++)
        #pragma unroll
        for (int r = 0; r < 4; r++) oacc[nt][r] = 0.f;
    float mrow[2] = {-1e30f, -1e30f};
    float lrow[2] = {0.f, 0.f};

    for (int kt = 0; kt <= qt; kt++) {
        __syncthreads();   // previous iteration's Ks/Vs reads complete
        const float* kg = Kp + (rowbase + kt * 64) * D_MODEL + h * D_HEAD;
        const float* vg = Vp + (rowbase + kt * 64) * D_MODEL + h * D_HEAD;
        #pragma unroll
        for (int i = 0; i < 8; i++) {
            int idx = tid + i * 128;
            int r = idx >> 4, c4 = idx & 15;
            float4 kv = *(const float4*)(kg + (size_t)r * D_MODEL + c4 * 4);
            uint32_t* dk = Ks + r * KST + c4 * 4;
            dk[0] = f2tf32(kv.x); dk[1] = f2tf32(kv.y);
            dk[2] = f2tf32(kv.z); dk[3] = f2tf32(kv.w);
            float4 vv = *(const float4*)(vg + (size_t)r * D_MODEL + c4 * 4);
            uint32_t* dv = Vs + r * VST + c4 * 4;
            dv[0] = f2tf32(vv.x); dv[1] = f2tf32(vv.y);
            dv[2] = f2tf32(vv.z); dv[3] = f2tf32(vv.w);
        }
        if (tid < 64)
            cs[tid] = Cdec[(rowbase + kt * 64 + tid) * N_HEADS + h];
        __syncthreads();

        // S = Q K^T  (B frag: b0 = K[n0+gid][ks*8+tig])
        float s[8][4];
        #pragma unroll
        for (int nt = 0; nt < 8; nt++)
            #pragma unroll
            for (int r = 0; r < 4; r++) s[nt][r] = 0.f;
        #pragma unroll
        for (int ks = 0; ks < 8; ks++) {
            #pragma unroll
            for (int nt = 0; nt < 8; nt++) {
                uint32_t b0 = Ks[(nt * 8 + gid) * KST + ks * 8 + tig];
                uint32_t b1 = Ks[(nt * 8 + gid) * KST + ks * 8 + tig + 4];
                mma_tf32(s[nt], qf[ks], b0, b1);
            }
        }

        // scale + decay + mask + online softmax (per thread: rows r0, r0+8)
        #pragma unroll
        for (int rr = 0; rr < 2; rr++) {
            int rloc = r0 + rr * 8;
            float mx = -1e30f;
            #pragma unroll
            for (int nt = 0; nt < 8; nt++) {
                #pragma unroll
                for (int q = 0; q < 2; q++) {
                    int col = nt * 8 + tig * 2 + q;
                    float val = s[nt][rr * 2 + q] * 0.125f - cs[col];
                    if (kt == qt && col > rloc) val = -1e30f;
                    s[nt][rr * 2 + q] = val;
                    mx = fmaxf(mx, val);
                }
            }
            mx = fmaxf(mx, __shfl_xor_sync(0xffffffffu, mx, 1));
            mx = fmaxf(mx, __shfl_xor_sync(0xffffffffu, mx, 2));
            float mnew = fmaxf(mrow[rr], mx);
            float sf = __expf(mrow[rr] - mnew);
            mrow[rr] = mnew;
            float rs = 0.f;
            #pragma unroll
            for (int nt = 0; nt < 8; nt++) {
                #pragma unroll
                for (int q = 0; q < 2; q++) {
                    float p = __expf(s[nt][rr * 2 + q] - mnew);
                    s[nt][rr * 2 + q] = p;
                    rs += p;
                }
            }
            rs += __shfl_xor_sync(0xffffffffu, rs, 1);
            rs += __shfl_xor_sync(0xffffffffu, rs, 2);
            lrow[rr] = lrow[rr] * sf + rs;
            #pragma unroll
            for (int nt = 0; nt < 8; nt++) {
                oacc[nt][rr * 2]     *= sf;
                oacc[nt][rr * 2 + 1] *= sf;
            }
        }

        // P -> smem (tf32), warp-private rows
        #pragma unroll
        for (int nt = 0; nt < 8; nt++) {
            uint2 p01 = make_uint2(f2tf32(s[nt][0]), f2tf32(s[nt][1]));
            *(uint2*)&Ps[(r0)     * PST + nt * 8 + tig * 2] = p01;
            uint2 p23 = make_uint2(f2tf32(s[nt][2]), f2tf32(s[nt][3]));
            *(uint2*)&Ps[(r0 + 8) * PST + nt * 8 + tig * 2] = p23;
        }
        __syncwarp();

        // O += P @ V
        #pragma unroll
        for (int ks = 0; ks < 8; ks++) {
            uint32_t af[4];
            af[0] = Ps[(r0)     * PST + ks * 8 + tig];
            af[1] = Ps[(r0 + 8) * PST + ks * 8 + tig];
            af[2] = Ps[(r0)     * PST + ks * 8 + tig + 4];
            af[3] = Ps[(r0 + 8) * PST + ks * 8 + tig + 4];
            #pragma unroll
            for (int nt = 0; nt < 8; nt++) {
                uint32_t b0 = Vs[(ks * 8 + tig)     * VST + nt * 8 + gid];
                uint32_t b1 = Vs[(ks * 8 + tig + 4) * VST + nt * 8 + gid];
                mma_tf32(oacc[nt], af, b0, b1);
            }
        }
    }

    // epilogue: divide by l, write
    float inv0 = 1.0f / lrow[0], inv1 = 1.0f / lrow[1];
    size_t row0 = rowbase + qbase + r0;
    #pragma unroll
    for (int nt = 0; nt < 8; nt++) {
        int col = h * D_HEAD + nt * 8 + tig * 2;
        *(float2*)(Out + row0 * D_MODEL + col) =
            make_float2(oacc[nt][0] * inv0, oacc[nt][1] * inv0);
        *(float2*)(Out + (row0 + 8) * D_MODEL + col) =
            make_float2(oacc[nt][2] * inv1, oacc[nt][3] * inv1);
    }
}

// ---------------- launcher ----------------
extern "C" void kernel_launch(void* const* d_in, const int* in_sizes, int n_in,
                              void* d_out, int out_size)
{
    const float* x    = (const float*)d_in[0];
    const float* ln1g = (const float*)d_in[1];
    const float* ln1b = (const float*)d_in[2];
    const float* wq   = (const float*)d_in[3];
    const float* bq   = (const float*)d_in[4];
    const float* wk   = (const float*)d_in[5];
    const float* bk   = (const float*)d_in[6];
    const float* wv   = (const float*)d_in[7];
    const float* bv   = (const float*)d_in[8];
    const float* wo   = (const float*)d_in[9];
    const float* bo   = (const float*)d_in[10];
    const float* wf   = (const float*)d_in[11];
    const float* bf   = (const float*)d_in[12];
    const float* ln2g = (const float*)d_in[13];
    const float* ln2b = (const float*)d_in[14];
    const float* w1   = (const float*)d_in[15];
    const float* b1   = (const float*)d_in[16];
    const float* w2   = (const float*)d_in[17];
    const float* b2   = (const float*)d_in[18];
    float* out = (float*)d_out;

    float *h, *q, *k, *v, *c, *ctx, *x1, *h2, *ff;
    cudaGetSymbolAddress((void**)&h,   g_h);
    cudaGetSymbolAddress((void**)&q,   g_q);
    cudaGetSymbolAddress((void**)&k,   g_k);
    cudaGetSymbolAddress((void**)&v,   g_v);
    cudaGetSymbolAddress((void**)&c,   g_c);
    cudaGetSymbolAddress((void**)&ctx, g_ctx);
    cudaGetSymbolAddress((void**)&x1,  g_x1);
    cudaGetSymbolAddress((void**)&h2,  g_h2);
    cudaGetSymbolAddress((void**)&ff,  g_ff);

    static int inited = 0;
    if (!inited) {
        cudaFuncSetAttribute(gemm_tc, cudaFuncAttributeMaxDynamicSharedMemorySize, GEMM_SMEM);
        cudaFuncSetAttribute(attn_tc, cudaFuncAttributeMaxDynamicSharedMemorySize, ATTN_SMEM);
        inited = 1;
    }

    // 1) LN1
    ln_kernel<<<NTOK, 256>>>(x, ln1g, ln1b, h);
    // 2-4) Q, K, V projections
    gemm_tc<<<dim3(D_MODEL/BN, NTOK/BM), 256, GEMM_SMEM>>>(h, wq, bq, nullptr, q, NTOK, D_MODEL, D_MODEL, 0);
    gemm_tc<<<dim3(D_MODEL/BN, NTOK/BM), 256, GEMM_SMEM>>>(h, wk, bk, nullptr, k, NTOK, D_MODEL, D_MODEL, 0);
    gemm_tc<<<dim3(D_MODEL/BN, NTOK/BM), 256, GEMM_SMEM>>>(h, wv, bv, nullptr, v, NTOK, D_MODEL, D_MODEL, 0);
    // 5) forget gate + 6) cumulative log-decay
    fgate_kernel<<<NTOK, 256>>>(h, wf, bf, c);
    cumsum_kernel<<<BATCH * N_HEADS, 256>>>(c);
    // 7) attention (tensor cores)
    attn_tc<<<dim3(SEQ/64, N_HEADS, BATCH), 128, ATTN_SMEM>>>(q, k, v, c, ctx);
    // 8) output proj + residual
    gemm_tc<<<dim3(D_MODEL/BN, NTOK/BM), 256, GEMM_SMEM>>>(ctx, wo, bo, x, x1, NTOK, D_MODEL, D_MODEL, 0);
    // 9) LN2
    ln_kernel<<<NTOK, 256>>>(x1, ln2g, ln2b, h2);
    // 10) FF up + GELU
    gemm_tc<<<dim3(D_FF/BN, NTOK/BM), 256, GEMM_SMEM>>>(h2, w1, b1, nullptr, ff, NTOK, D_FF, D_MODEL, 1);
    // 11) FF down + residual -> output
    gemm_tc<<<dim3(D_MODEL/BN, NTOK/BM), 256, GEMM_SMEM>>>(ff, w2, b2, x1, out, NTOK, D_MODEL, D_FF, 0);
}

// round 4
// speedup vs baseline: 4.1317x; 1.2244x over previous
#include <cuda_runtime.h>
#include <math.h>
#include <stdint.h>

#define D_MODEL 1024
#define N_HEADS 16
#define D_HEAD  64
#define D_FF    4096
#define BATCH   2
#define SEQ     2048
#define NTOK    (BATCH*SEQ)

// ---------------- scratch (no cudaMalloc allowed) ----------------
__device__ float g_h  [NTOK*D_MODEL];
__device__ float g_q  [NTOK*D_MODEL];
__device__ float g_k  [NTOK*D_MODEL];
__device__ float g_v  [NTOK*D_MODEL];
__device__ float g_c  [NTOK*N_HEADS];
__device__ float g_ctx[NTOK*D_MODEL];
__device__ float g_x1 [NTOK*D_MODEL];
__device__ float g_h2 [NTOK*D_MODEL];
__device__ float g_ff [NTOK*D_FF];
// rounded weight copies
__device__ float g_wq[D_MODEL*D_MODEL];
__device__ float g_wk[D_MODEL*D_MODEL];
__device__ float g_wv[D_MODEL*D_MODEL];
__device__ float g_wo[D_MODEL*D_MODEL];
__device__ float g_w1[D_MODEL*D_FF];
__device__ float g_w2[D_FF*D_MODEL];

__device__ __forceinline__ uint32_t f2tf32(float x) {
    uint32_t r;
    asm("cvt.rna.tf32.f32 %0, %1;" : "=r"(r) : "f"(x));
    return r;
}
__device__ __forceinline__ float ftf32(float x) {
    return __uint_as_float(f2tf32(x));
}
__device__ __forceinline__ void cp16(uint32_t dst, const void* src) {
    asm volatile("cp.async.cg.shared.global [%0], [%1], 16;" :: "r"(dst), "l"(src));
}
#define CP_COMMIT() asm volatile("cp.async.commit_group;")
#define CP_WAIT0()  asm volatile("cp.async.wait_group 0;")

__device__ __forceinline__ void mma_tf32(float* c, const uint32_t* a,
                                         uint32_t b0, uint32_t b1) {
    asm volatile(
        "mma.sync.aligned.m16n8k8.row.col.f32.tf32.tf32.f32 "
        "{%0,%1,%2,%3}, {%4,%5,%6,%7}, {%8,%9}, {%0,%1,%2,%3};"
        : "+f"(c[0]), "+f"(c[1]), "+f"(c[2]), "+f"(c[3])
        : "r"(a[0]), "r"(a[1]), "r"(a[2]), "r"(a[3]), "r"(b0), "r"(b1));
}

__device__ __forceinline__ float gelu_exact(float x) {
    return 0.5f * x * (1.0f + erff(x * 0.70710678118654752f));
}

// ---------------- tf32 rounding pass (weights) ----------------
__global__ __launch_bounds__(256) void round_tf32_kernel(
    const float* __restrict__ src, float* __restrict__ dst, int n4)
{
    int i = blockIdx.x * 256 + threadIdx.x;
    if (i < n4) {
        float4 v = ((const float4*)src)[i];
        v.x = ftf32(v.x); v.y = ftf32(v.y);
        v.z = ftf32(v.z); v.w = ftf32(v.w);
        ((float4*)dst)[i] = v;
    }
}

// ---------------- LayerNorm (tf32-rounded output) ----------------
__global__ __launch_bounds__(256) void ln_kernel(
    const float* __restrict__ x, const float* __restrict__ g,
    const float* __restrict__ b, float* __restrict__ out)
{
    int row = blockIdx.x;
    int tid = threadIdx.x;
    const float4* xr = (const float4*)(x + (size_t)row * D_MODEL);
    float4 v = xr[tid];
    float s  = v.x + v.y + v.z + v.w;
    float s2 = v.x*v.x + v.y*v.y + v.z*v.z + v.w*v.w;

    __shared__ float red[18];
    #pragma unroll
    for (int off = 16; off > 0; off >>= 1) {
        s  += __shfl_xor_sync(0xffffffffu, s,  off);
        s2 += __shfl_xor_sync(0xffffffffu, s2, off);
    }
    int w = tid >> 5, lane = tid & 31;
    if (lane == 0) { red[w] = s; red[8 + w] = s2; }
    __syncthreads();
    if (tid == 0) {
        float a = 0.f, c2 = 0.f;
        #pragma unroll
        for (int i = 0; i < 8; i++) { a += red[i]; c2 += red[8 + i]; }
        red[16] = a; red[17] = c2;
    }
    __syncthreads();
    float mu  = red[16] * (1.0f / D_MODEL);
    float var = red[17] * (1.0f / D_MODEL) - mu * mu;
    float inv = rsqrtf(var + 1e-5f);

    float4 gg = ((const float4*)g)[tid];
    float4 bb = ((const float4*)b)[tid];
    float4 o;
    o.x = ftf32((v.x - mu) * inv * gg.x + bb.x);
    o.y = ftf32((v.y - mu) * inv * gg.y + bb.y);
    o.z = ftf32((v.z - mu) * inv * gg.z + bb.z);
    o.w = ftf32((v.w - mu) * inv * gg.w + bb.w);
    ((float4*)(out + (size_t)row * D_MODEL))[tid] = o;
}

// ---------------- TF32 tensor-core GEMM, cp.async double-buffered ----------------
// Inputs A,W must already be tf32-rounded (mma truncation is then exact).
#define BM 128
#define BN 128
#define BK 32
#define AST 36
#define BST 136
#define ASZ (BM*AST)
#define BSZ (BK*BST)
#define GEMM_SMEM ((2*ASZ + 2*BSZ) * 4)

__global__ __launch_bounds__(256, 2) void gemm_tc(
    const float* __restrict__ A, const float* __restrict__ W,
    const float* __restrict__ bias, const float* __restrict__ resid,
    float* __restrict__ C, int M, int N, int K, int act, int rnd)
{
    extern __shared__ uint32_t dsm[];
    uint32_t* As = dsm;
    uint32_t* Bs = dsm + 2*ASZ;

    int tid  = threadIdx.x;
    int wid  = tid >> 5, lane = tid & 31;
    int warp_m = wid >> 2;
    int warp_n = wid & 3;
    int gid = lane >> 2, tig = lane & 3;
    int mb = blockIdx.y * BM, nb = blockIdx.x * BN;

    float acc[4][4][4];
    #pragma unroll
    for (int mt = 0; mt < 4; mt++)
        #pragma unroll
        for (int nt = 0; nt < 4; nt++)
            #pragma unroll
            for (int r = 0; r < 4; r++) acc[mt][nt][r] = 0.f;

    const float* a_gp[4];
    uint32_t a_dst[4];
    #pragma unroll
    for (int i = 0; i < 4; i++) {
        int idx = tid + i * 256;
        int m = idx >> 3;
        int kg = ((idx & 7) + 8 - (m & 7)) & 7;
        a_gp[i] = A + (size_t)(mb + m) * K + kg * 4;
        a_dst[i] = (uint32_t)__cvta_generic_to_shared(&As[m * AST + kg * 4]);
    }
    const float* b_gp[4];
    uint32_t b_dst[4];
    #pragma unroll
    for (int i = 0; i < 4; i++) {
        int idx = tid + i * 256;
        int k = idx >> 5, ng = idx & 31;
        b_gp[i] = W + (size_t)k * N + nb + ng * 4;
        b_dst[i] = (uint32_t)__cvta_generic_to_shared(&Bs[k * BST + ng * 4]);
    }

    int lm_row = ((lane >> 3) & 1) * 8 + (lane & 7);
    int lm_khalf = (lane >> 4);
    // per-mt ldmatrix base address (buffer 0, ks=0)
    uint32_t lm_base[4];
    #pragma unroll
    for (int mt = 0; mt < 4; mt++) {
        int row = warp_m * 64 + mt * 16 + lm_row;
        lm_base[mt] = (uint32_t)__cvta_generic_to_shared(
            &As[row * AST + lm_khalf * 4]);
    }
    // B fragment base index (buffer 0, ks=0)
    int bf_base = tig * BST + warp_n * 32 + gid;

    // prologue
    #pragma unroll
    for (int i = 0; i < 4; i++) cp16(a_dst[i], a_gp[i]);
    #pragma unroll
    for (int i = 0; i < 4; i++) cp16(b_dst[i], b_gp[i]);
    CP_COMMIT();

    int buf = 0;
    for (int k0 = 0; k0 < K; k0 += BK) {
        CP_WAIT0();
        __syncthreads();
        if (k0 + BK < K) {
            int nbo = (buf ^ 1);
            #pragma unroll
            for (int i = 0; i < 4; i++)
                cp16(a_dst[i] + nbo * ASZ * 4, a_gp[i] + k0 + BK);
            #pragma unroll
            for (int i = 0; i < 4; i++)
                cp16(b_dst[i] + nbo * BSZ * 4, b_gp[i] + (size_t)(k0 + BK) * N);
            CP_COMMIT();
        }

        const uint32_t* Bb = Bs + buf * BSZ;
        uint32_t abuf_ofs = buf * ASZ * 4;
        #pragma unroll
        for (int ks = 0; ks < 4; ks++) {
            uint32_t af[4][4];
            #pragma unroll
            for (int mt = 0; mt < 4; mt++) {
                uint32_t saddr = lm_base[mt] + abuf_ofs + ks * 32;
                asm volatile(
                    "ldmatrix.sync.aligned.m8n8.x4.shared.b16 {%0,%1,%2,%3}, [%4];"
                    : "=r"(af[mt][0]), "=r"(af[mt][1]),
                      "=r"(af[mt][2]), "=r"(af[mt][3])
                    : "r"(saddr));
            }
            uint32_t bf[4][2];
            #pragma unroll
            for (int nt = 0; nt < 4; nt++) {
                bf[nt][0] = Bb[bf_base + ks * 8 * BST + nt * 8];
                bf[nt][1] = Bb[bf_base + (ks * 8 + 4) * BST + nt * 8];
            }
            #pragma unroll
            for (int mt = 0; mt < 4; mt++)
                #pragma unroll
                for (int nt = 0; nt < 4; nt++)
                    mma_tf32(acc[mt][nt], af[mt], bf[nt][0], bf[nt][1]);
        }
        buf ^= 1;
    }

    // epilogue
    #pragma unroll
    for (int mt = 0; mt < 4; mt++) {
        int r0 = mb + warp_m * 64 + mt * 16 + gid;
        int r1 = r0 + 8;
        #pragma unroll
        for (int nt = 0; nt < 4; nt++) {
            int cc = nb + warp_n * 32 + nt * 8 + tig * 2;
            float b0 = bias[cc], b1 = bias[cc + 1];
            float v00 = acc[mt][nt][0] + b0, v01 = acc[mt][nt][1] + b1;
            float v10 = acc[mt][nt][2] + b0, v11 = acc[mt][nt][3] + b1;
            if (act == 1) {
                v00 = gelu_exact(v00); v01 = gelu_exact(v01);
                v10 = gelu_exact(v10); v11 = gelu_exact(v11);
            }
            size_t p0 = (size_t)r0 * N + cc;
            size_t p1 = (size_t)r1 * N + cc;
            if (resid) {
                float2 q0 = *(const float2*)(resid + p0);
                float2 q1 = *(const float2*)(resid + p1);
                v00 += q0.x; v01 += q0.y; v10 += q1.x; v11 += q1.y;
            }
            if (rnd) {
                v00 = ftf32(v00); v01 = ftf32(v01);
                v10 = ftf32(v10); v11 = ftf32(v11);
            }
            *(float2*)(C + p0) = make_float2(v00, v01);
            *(float2*)(C + p1) = make_float2(v10, v11);
        }
    }
}

// ---------------- forget gate ----------------
__global__ __launch_bounds__(256) void fgate_kernel(
    const float* __restrict__ h, const float* __restrict__ wf,
    const float* __restrict__ bf, float* __restrict__ logf)
{
    int t   = blockIdx.x;
    int tid = threadIdx.x;
    int hd  = tid >> 4;
    int ln  = tid & 15;
    const float* hr = h + (size_t)t * D_MODEL;
    float s = 0.f;
    #pragma unroll 8
    for (int k = ln; k < D_MODEL; k += 16)
        s = fmaf(hr[k], wf[(size_t)k * N_HEADS + hd], s);
    #pragma unroll
    for (int off = 8; off > 0; off >>= 1)
        s += __shfl_xor_sync(0xffffffffu, s, off);
    if (ln == 0) {
        float z = s + bf[hd];
        float ls = (z >= 0.f) ? -log1pf(expf(-z)) : (z - log1pf(expf(z)));
        logf[(size_t)t * N_HEADS + hd] = ls;
    }
}

// ---------------- cumsum per (b,h) ----------------
__global__ __launch_bounds__(256) void cumsum_kernel(float* __restrict__ c)
{
    int bh = blockIdx.x;
    int b  = bh >> 4, h = bh & 15;
    int tid = threadIdx.x;
    const int CHUNK = SEQ / 256;
    float vals[CHUNK];
    float run = 0.f;
    size_t base = (size_t)b * SEQ * N_HEADS + h;
    #pragma unroll
    for (int u = 0; u < CHUNK; u++) {
        run += c[base + (size_t)(tid * CHUNK + u) * N_HEADS];
        vals[u] = run;
    }
    __shared__ float tot[256];
    tot[tid] = run;
    __syncthreads();
    for (int off = 1; off < 256; off <<= 1) {
        float t = (tid >= off) ? tot[tid - off] : 0.f;
        __syncthreads();
        tot[tid] += t;
        __syncthreads();
    }
    float offs = tot[tid] - run;
    #pragma unroll
    for (int u = 0; u < CHUNK; u++)
        c[base + (size_t)(tid * CHUNK + u) * N_HEADS] = vals[u] + offs;
}

// ---------------- tensor-core flash attention with forgetting decay ----------------
// Q/K/V already tf32-rounded. logits = (q.k)/8 - c_j (c_i dropped: softmax-invariant).
#define KST 68
#define VST 72
#define PST 68
#define ATTN_SMEM ((64*KST + 64*VST + 64*PST + 64) * 4)

__global__ __launch_bounds__(128) void attn_tc(
    const float* __restrict__ Q, const float* __restrict__ Kp,
    const float* __restrict__ Vp, const float* __restrict__ Cdec,
    float* __restrict__ Out)
{
    extern __shared__ float sm[];
    uint32_t* Ks = (uint32_t*)sm;            // [64][KST]
    uint32_t* Vs = Ks + 64 * KST;            // [64][VST]
    uint32_t* Ps = Vs + 64 * VST;            // [64][PST] (Q staging, then P)
    float*    cs = (float*)(Ps + 64 * PST);  // [64]

    int qt = blockIdx.x, h = blockIdx.y, b = blockIdx.z;
    int tid = threadIdx.x, wid = tid >> 5, lane = tid & 31;
    int gid = lane >> 2, tig = lane & 3;
    size_t rowbase = (size_t)b * SEQ;
    int qbase = qt * 64;
    int r0 = wid * 16 + gid;

    // per-thread staging addresses (r, c4)
    int sidx = tid, sr = sidx >> 4, sc4 = sidx & 15;
    int sidx2 = tid + 128, sr2 = sidx2 >> 4, sc42 = sidx2 & 15;
    // (8 iterations of 128 threads cover 64x16 float4 slots)

    // stage Q via cp.async into Ps
    const float* qg = Q + (rowbase + qbase) * D_MODEL + h * D_HEAD;
    #pragma unroll
    for (int i = 0; i < 8; i++) {
        int idx = tid + i * 128;
        int r = idx >> 4, c4 = idx & 15;
        cp16((uint32_t)__cvta_generic_to_shared(Ps + r * PST + c4 * 4),
             qg + (size_t)r * D_MODEL + c4 * 4);
    }
    CP_COMMIT(); CP_WAIT0();
    __syncthreads();

    uint32_t qf[8][4];
    #pragma unroll
    for (int ks = 0; ks < 8; ks++) {
        qf[ks][0] = Ps[(r0)     * PST + ks * 8 + tig];
        qf[ks][1] = Ps[(r0 + 8) * PST + ks * 8 + tig];
        qf[ks][2] = Ps[(r0)     * PST + ks * 8 + tig + 4];
        qf[ks][3] = Ps[(r0 + 8) * PST + ks * 8 + tig + 4];
    }

    float oacc[8][4];
    #pragma unroll
    for (int nt = 0; nt < 8; nt++)
        #pragma unroll
        for (int r = 0; r < 4; r++) oacc[nt][r] = 0.f;
    float mrow[2] = {-1e30f, -1e30f};
    float lrow[2] = {0.f, 0.f};

    for (int kt = 0; kt <= qt; kt++) {
        __syncthreads();
        const float* kg = Kp + (rowbase + kt * 64) * D_MODEL + h * D_HEAD;
        const float* vg = Vp + (rowbase + kt * 64) * D_MODEL + h * D_HEAD;
        #pragma unroll
        for (int i = 0; i < 8; i++) {
            int idx = tid + i * 128;
            int r = idx >> 4, c4 = idx & 15;
            cp16((uint32_t)__cvta_generic_to_shared(Ks + r * KST + c4 * 4),
                 kg + (size_t)r * D_MODEL + c4 * 4);
            cp16((uint32_t)__cvta_generic_to_shared(Vs + r * VST + c4 * 4),
                 vg + (size_t)r * D_MODEL + c4 * 4);
        }
        CP_COMMIT();
        if (tid < 64)
            cs[tid] = Cdec[(rowbase + kt * 64 + tid) * N_HEADS + h];
        CP_WAIT0();
        __syncthreads();

        // S = Q K^T
        float s[8][4];
        #pragma unroll
        for (int nt = 0; nt < 8; nt++)
            #pragma unroll
            for (int r = 0; r < 4; r++) s[nt][r] = 0.f;
        #pragma unroll
        for (int ks = 0; ks < 8; ks++) {
            #pragma unroll
            for (int nt = 0; nt < 8; nt++) {
                uint32_t b0 = Ks[(nt * 8 + gid) * KST + ks * 8 + tig];
                uint32_t b1 = Ks[(nt * 8 + gid) * KST + ks * 8 + tig + 4];
                mma_tf32(s[nt], qf[ks], b0, b1);
            }
        }

        // scale + decay + mask + online softmax
        #pragma unroll
        for (int rr = 0; rr < 2; rr++) {
            int rloc = r0 + rr * 8;
            float mx = -1e30f;
            #pragma unroll
            for (int nt = 0; nt < 8; nt++) {
                #pragma unroll
                for (int q = 0; q < 2; q++) {
                    int col = nt * 8 + tig * 2 + q;
                    float val = s[nt][rr * 2 + q] * 0.125f - cs[col];
                    if (kt == qt && col > rloc) val = -1e30f;
                    s[nt][rr * 2 + q] = val;
                    mx = fmaxf(mx, val);
                }
            }
            mx = fmaxf(mx, __shfl_xor_sync(0xffffffffu, mx, 1));
            mx = fmaxf(mx, __shfl_xor_sync(0xffffffffu, mx, 2));
            float mnew = fmaxf(mrow[rr], mx);
            float sf = __expf(mrow[rr] - mnew);
            mrow[rr] = mnew;
            float rs = 0.f;
            #pragma unroll
            for (int nt = 0; nt < 8; nt++) {
                #pragma unroll
                for (int q = 0; q < 2; q++) {
                    float p = __expf(s[nt][rr * 2 + q] - mnew);
                    s[nt][rr * 2 + q] = p;
                    rs += p;
                }
            }
            rs += __shfl_xor_sync(0xffffffffu, rs, 1);
            rs += __shfl_xor_sync(0xffffffffu, rs, 2);
            lrow[rr] = lrow[rr] * sf + rs;
            #pragma unroll
            for (int nt = 0; nt < 8; nt++) {
                oacc[nt][rr * 2]     *= sf;
                oacc[nt][rr * 2 + 1] *= sf;
            }
        }

        // P -> smem (tf32), warp-private rows
        #pragma unroll
        for (int nt = 0; nt < 8; nt++) {
            uint2 p01 = make_uint2(f2tf32(s[nt][0]), f2tf32(s[nt][1]));
            *(uint2*)&Ps[(r0)     * PST + nt * 8 + tig * 2] = p01;
            uint2 p23 = make_uint2(f2tf32(s[nt][2]), f2tf32(s[nt][3]));
            *(uint2*)&Ps[(r0 + 8) * PST + nt * 8 + tig * 2] = p23;
        }
        __syncwarp();

        // O += P @ V
        #pragma unroll
        for (int ks = 0; ks < 8; ks++) {
            uint32_t af[4];
            af[0] = Ps[(r0)     * PST + ks * 8 + tig];
            af[1] = Ps[(r0 + 8) * PST + ks * 8 + tig];
            af[2] = Ps[(r0)     * PST + ks * 8 + tig + 4];
            af[3] = Ps[(r0 + 8) * PST + ks * 8 + tig + 4];
            #pragma unroll
            for (int nt = 0; nt < 8; nt++) {
                uint32_t b0 = Vs[(ks * 8 + tig)     * VST + nt * 8 + gid];
                uint32_t b1 = Vs[(ks * 8 + tig + 4) * VST + nt * 8 + gid];
                mma_tf32(oacc[nt], af, b0, b1);
            }
        }
    }

    // epilogue: divide by l, round to tf32 (feeds Wo GEMM), write
    float inv0 = 1.0f / lrow[0], inv1 = 1.0f / lrow[1];
    size_t row0 = rowbase + qbase + r0;
    #pragma unroll
    for (int nt = 0; nt < 8; nt++) {
        int col = h * D_HEAD + nt * 8 + tig * 2;
        *(float2*)(Out + row0 * D_MODEL + col) =
            make_float2(ftf32(oacc[nt][0] * inv0), ftf32(oacc[nt][1] * inv0));
        *(float2*)(Out + (row0 + 8) * D_MODEL + col) =
            make_float2(ftf32(oacc[nt][2] * inv1), ftf32(oacc[nt][3] * inv1));
    }
}

// ---------------- launcher ----------------
extern "C" void kernel_launch(void* const* d_in, const int* in_sizes, int n_in,
                              void* d_out, int out_size)
{
    const float* x    = (const float*)d_in[0];
    const float* ln1g = (const float*)d_in[1];
    const float* ln1b = (const float*)d_in[2];
    const float* wq   = (const float*)d_in[3];
    const float* bq   = (const float*)d_in[4];
    const float* wk   = (const float*)d_in[5];
    const float* bk   = (const float*)d_in[6];
    const float* wv   = (const float*)d_in[7];
    const float* bv   = (const float*)d_in[8];
    const float* wo   = (const float*)d_in[9];
    const float* bo   = (const float*)d_in[10];
    const float* wf   = (const float*)d_in[11];
    const float* bf   = (const float*)d_in[12];
    const float* ln2g = (const float*)d_in[13];
    const float* ln2b = (const float*)d_in[14];
    const float* w1   = (const float*)d_in[15];
    const float* b1   = (const float*)d_in[16];
    const float* w2   = (const float*)d_in[17];
    const float* b2   = (const float*)d_in[18];
    float* out = (float*)d_out;

    float *h, *q, *k, *v, *c, *ctx, *x1, *h2, *ff;
    float *rwq, *rwk, *rwv, *rwo, *rw1, *rw2;
    cudaGetSymbolAddress((void**)&h,   g_h);
    cudaGetSymbolAddress((void**)&q,   g_q);
    cudaGetSymbolAddress((void**)&k,   g_k);
    cudaGetSymbolAddress((void**)&v,   g_v);
    cudaGetSymbolAddress((void**)&c,   g_c);
    cudaGetSymbolAddress((void**)&ctx, g_ctx);
    cudaGetSymbolAddress((void**)&x1,  g_x1);
    cudaGetSymbolAddress((void**)&h2,  g_h2);
    cudaGetSymbolAddress((void**)&ff,  g_ff);
    cudaGetSymbolAddress((void**)&rwq, g_wq);
    cudaGetSymbolAddress((void**)&rwk, g_wk);
    cudaGetSymbolAddress((void**)&rwv, g_wv);
    cudaGetSymbolAddress((void**)&rwo, g_wo);
    cudaGetSymbolAddress((void**)&rw1, g_w1);
    cudaGetSymbolAddress((void**)&rw2, g_w2);

    static int inited = 0;
    if (!inited) {
        cudaFuncSetAttribute(gemm_tc, cudaFuncAttributeMaxDynamicSharedMemorySize, GEMM_SMEM);
        cudaFuncSetAttribute(attn_tc, cudaFuncAttributeMaxDynamicSharedMemorySize, ATTN_SMEM);
        inited = 1;
    }

    // 0) round weights to tf32-representable fp32
    int n4a = D_MODEL * D_MODEL / 4;
    int n4b = D_MODEL * D_FF / 4;
    round_tf32_kernel<<<(n4a + 255) / 256, 256>>>(wq, rwq, n4a);
    round_tf32_kernel<<<(n4a + 255) / 256, 256>>>(wk, rwk, n4a);
    round_tf32_kernel<<<(n4a + 255) / 256, 256>>>(wv, rwv, n4a);
    round_tf32_kernel<<<(n4a + 255) / 256, 256>>>(wo, rwo, n4a);
    round_tf32_kernel<<<(n4b + 255) / 256, 256>>>(w1, rw1, n4b);
    round_tf32_kernel<<<(n4b + 255) / 256, 256>>>(w2, rw2, n4b);

    // 1) LN1 (tf32-rounded h)
    ln_kernel<<<NTOK, 256>>>(x, ln1g, ln1b, h);
    // 2-4) Q, K, V projections (rounded outputs feed attention mma)
    gemm_tc<<<dim3(D_MODEL/BN, NTOK/BM), 256, GEMM_SMEM>>>(h, rwq, bq, nullptr, q, NTOK, D_MODEL, D_MODEL, 0, 1);
    gemm_tc<<<dim3(D_MODEL/BN, NTOK/BM), 256, GEMM_SMEM>>>(h, rwk, bk, nullptr, k, NTOK, D_MODEL, D_MODEL, 0, 1);
    gemm_tc<<<dim3(D_MODEL/BN, NTOK/BM), 256, GEMM_SMEM>>>(h, rwv, bv, nullptr, v, NTOK, D_MODEL, D_MODEL, 0, 1);
    // 5) forget gate + 6) cumulative log-decay
    fgate_kernel<<<NTOK, 256>>>(h, wf, bf, c);
    cumsum_kernel<<<BATCH * N_HEADS, 256>>>(c);
    // 7) attention (tensor cores; ctx rounded in epilogue)
    attn_tc<<<dim3(SEQ/64, N_HEADS, BATCH), 128, ATTN_SMEM>>>(q, k, v, c, ctx);
    // 8) output proj + residual (fp32 output)
    gemm_tc<<<dim3(D_MODEL/BN, NTOK/BM), 256, GEMM_SMEM>>>(ctx, rwo, bo, x, x1, NTOK, D_MODEL, D_MODEL, 0, 0);
    // 9) LN2 (rounded h2)
    ln_kernel<<<NTOK, 256>>>(x1, ln2g, ln2b, h2);
    // 10) FF up + GELU (rounded ff)
    gemm_tc<<<dim3(D_FF/BN, NTOK/BM), 256, GEMM_SMEM>>>(h2, rw1, b1, nullptr, ff, NTOK, D_FF, D_MODEL, 1, 1);
    // 11) FF down + residual -> output (fp32)
    gemm_tc<<<dim3(D_MODEL/BN, NTOK/BM), 256, GEMM_SMEM>>>(ff, rw2, b2, x1, out, NTOK, D_MODEL, D_FF, 0, 0);
}